// round 2
// baseline (speedup 1.0000x reference)
#include <cuda_runtime.h>
#include <cstdint>

// AcousticPhysicsEngine: out[idx_row[i]] += vals[i] * field.T.flat[idx_col[i]]
// field: [256,256] f32; idx_row/idx_col: [30M] int32 (JAX x64 disabled);
// vals: [30M] f32; out: [131072] f32 (reshape(1024,128) is a flat view).

__global__ void zero_out_kernel(float* __restrict__ out, int n) {
    int i = blockIdx.x * blockDim.x + threadIdx.x;
    if (i < n) out[i] = 0.0f;
}

__global__ void __launch_bounds__(256)
spmv_scatter_kernel(const float* __restrict__ field,
                    const int*   __restrict__ idx_row,
                    const int*   __restrict__ idx_col,
                    const float* __restrict__ vals,
                    float*       __restrict__ out,
                    long long nnz)
{
    long long tid    = (long long)blockIdx.x * blockDim.x + threadIdx.x;
    long long stride = (long long)gridDim.x * blockDim.x;

    long long nvec = nnz >> 2;  // groups of 4 nonzeros
    for (long long g = tid; g < nvec; g += stride) {
        long long base = g << 2;

        int4   r = *reinterpret_cast<const int4*>(idx_row + base);
        int4   c = *reinterpret_cast<const int4*>(idx_col + base);
        float4 v = *reinterpret_cast<const float4*>(vals + base);

        unsigned c0 = (unsigned)c.x, c1 = (unsigned)c.y;
        unsigned c2 = (unsigned)c.z, c3 = (unsigned)c.w;

        // column-major flatten: flat[c] = field[(c % 256) * 256 + (c / 256)]
        float f0 = __ldg(field + (((c0 & 255u) << 8) | (c0 >> 8)));
        float f1 = __ldg(field + (((c1 & 255u) << 8) | (c1 >> 8)));
        float f2 = __ldg(field + (((c2 & 255u) << 8) | (c2 >> 8)));
        float f3 = __ldg(field + (((c3 & 255u) << 8) | (c3 >> 8)));

        atomicAdd(out + (unsigned)r.x, v.x * f0);
        atomicAdd(out + (unsigned)r.y, v.y * f1);
        atomicAdd(out + (unsigned)r.z, v.z * f2);
        atomicAdd(out + (unsigned)r.w, v.w * f3);
    }

    // Tail (nnz % 4 != 0) — defensive; NNZ=30M is divisible by 4.
    long long tail_start = nvec << 2;
    for (long long i = tail_start + tid; i < nnz; i += stride) {
        unsigned cc = (unsigned)idx_col[i];
        float f = __ldg(field + (((cc & 255u) << 8) | (cc >> 8)));
        atomicAdd(out + (unsigned)idx_row[i], vals[i] * f);
    }
}

extern "C" void kernel_launch(void* const* d_in, const int* in_sizes, int n_in,
                              void* d_out, int out_size)
{
    const float* field   = (const float*)d_in[0];  // [65536]
    const int*   idx_row = (const int*)d_in[1];    // [NNZ] int32
    const int*   idx_col = (const int*)d_in[2];    // [NNZ] int32
    const float* vals    = (const float*)d_in[3];  // [NNZ]
    float* out = (float*)d_out;                    // [131072]
    long long nnz = (long long)in_sizes[1];

    {
        int threads = 256;
        int blocks = (out_size + threads - 1) / threads;
        zero_out_kernel<<<blocks, threads>>>(out, out_size);
    }
    {
        int threads = 256;
        long long nvec = nnz >> 2;
        long long want = (nvec + threads - 1) / threads;
        long long cap  = 148LL * 8;  // persistent-ish: plenty of blocks, grid-stride covers rest
        // Use enough blocks to saturate: target ~8 waves of work per thread.
        long long target = (nvec + 8 * threads - 1) / (8 * threads);
        int blocks = (int)(target < 1 ? 1 : (target > 148 * 32 ? 148 * 32 : target));
        (void)want; (void)cap;
        spmv_scatter_kernel<<<blocks, threads>>>(field, idx_row, idx_col, vals, out, nnz);
    }
}